// round 13
// baseline (speedup 1.0000x reference)
#include <cuda_runtime.h>
#include <cuda_fp16.h>
#include <math.h>
#include <stdint.h>

#define T_STEPS 8
#define NN      10000
#define EE      200000
#define FIN     32
#define HID     128
#define OUTD    64
#define G4      256            // 4*OUT
#define MROWS   (T_STEPS*NN)   // 80000
#define EPSBN   1e-5f

// weight-plane offsets ([n][k] fp16 layout, packed)
// LSTM planes (WO3.., WH..) use gate-interleaved row permutation:
//   plane row j = g*32 + q*8 + v  <->  torch row = q*64 + g*8 + v
#define WO0 0            // wg0^T   128x32
#define WO1 4096         // wg1^T   128x128
#define WO2 20480        // wg2^T   128x128
#define WO3 36864        // w_ih0   256x128 (perm)
#define WO4 69632        // w_ih1   256x64  (perm)
#define WO5 86016        // w_ih2   256x64  (perm)
#define WH0 102400       // whh0    256x64  (perm)
#define WH1 118784       // whh1    256x64  (perm)
#define WH2 135168       // whh2    256x64  (perm)
#define WTOT 151552
#define PREP_ELEMS (WTOT + 768)

// ===================== scratch (device globals) =====================
static __device__ __half g_preH[MROWS*G4];     // LSTM0 input projections (fp16, permuted)
static __device__ __half g_xH  [MROWS*FIN];    // x converted to fp16
static __device__ __half g_actA[MROWS*HID];    // ping
static __device__ __half g_actB[MROWS*HID];    // pong
static __device__ __half g_yA[MROWS*OUTD];
static __device__ __half g_yB[MROWS*OUTD];
static __device__ __half g_wH[WTOT];
static __device__ float g_biasc[3*G4];         // permuted
static __device__ float g_dis[NN];
static __device__ int   g_cnt[NN];
static __device__ int   g_rowptr[NN+1];
static __device__ int   g_cursor[NN];
static __device__ int   g_csr_src[EE];
static __device__ float g_csr_coef[EE];

// ===================== helpers =====================
__device__ __forceinline__ uint32_t smem_u32(const void* p) {
    uint32_t a;
    asm("{ .reg .u64 t; cvta.to.shared.u64 t, %1; cvt.u32.u64 %0, t; }" : "=r"(a) : "l"(p));
    return a;
}
__device__ __forceinline__ void cp16(uint32_t s, const void* g) {
    asm volatile("cp.async.cg.shared.global [%0], [%1], 16;" :: "r"(s), "l"(g));
}
__device__ __forceinline__ void cp_commit() {
    asm volatile("cp.async.commit_group;");
}
__device__ __forceinline__ void cp_wait0() {
    asm volatile("cp.async.wait_group 0;");
}
__device__ __forceinline__ void cp_wait1() {
    asm volatile("cp.async.wait_group 1;");
}
__device__ __forceinline__ void ldsm_x4(uint32_t* r, uint32_t addr) {
    asm volatile("ldmatrix.sync.aligned.m8n8.x4.shared.b16 {%0,%1,%2,%3}, [%4];"
                 : "=r"(r[0]), "=r"(r[1]), "=r"(r[2]), "=r"(r[3]) : "r"(addr));
}
__device__ __forceinline__ void mma16816(float* d, const uint32_t* a, const uint32_t* b) {
    asm volatile(
        "mma.sync.aligned.m16n8k16.row.col.f32.f16.f16.f32 "
        "{%0,%1,%2,%3}, {%4,%5,%6,%7}, {%8,%9}, {%0,%1,%2,%3};"
        : "+f"(d[0]), "+f"(d[1]), "+f"(d[2]), "+f"(d[3])
        : "r"(a[0]), "r"(a[1]), "r"(a[2]), "r"(a[3]), "r"(b[0]), "r"(b[1]));
}
__device__ __forceinline__ uint32_t pack_h2(float x, float y) {
    __half2 h = __floats2half2_rn(x, y);
    return *(uint32_t*)&h;
}
__device__ __forceinline__ float sigmoidf_(float x) {
    return 1.0f / (1.0f + __expf(-x));
}
__device__ __forceinline__ float tanhf_(float x) {
    return 1.0f - 2.0f / (__expf(2.0f * x) + 1.0f);
}

// ===================== setup kernels =====================
__global__ void k_zero_cnt() {
    int i = blockIdx.x * blockDim.x + threadIdx.x;
    if (i < NN) g_cnt[i] = 0;
}
__global__ void k_hist(const int* __restrict__ dst) {
    int e = blockIdx.x * blockDim.x + threadIdx.x;
    if (e < EE) atomicAdd(&g_cnt[dst[e]], 1);
}
__global__ void k_scanfused() {
    const int TPB = 1024, PER = 10;
    __shared__ int sh[TPB];
    int tid = threadIdx.x;
    for (int i = tid; i < NN; i += TPB) g_dis[i] = rsqrtf((float)g_cnt[i] + 1.0f);
    int base = tid * PER;
    int loc[PER];
    int s = 0;
#pragma unroll
    for (int i = 0; i < PER; i++) {
        int idx = base + i;
        int v = (idx < NN) ? g_cnt[idx] : 0;
        loc[i] = s; s += v;
    }
    sh[tid] = s; __syncthreads();
    for (int off = 1; off < TPB; off <<= 1) {
        int v = (tid >= off) ? sh[tid - off] : 0;
        __syncthreads();
        sh[tid] += v;
        __syncthreads();
    }
    int excl = (tid == 0) ? 0 : sh[tid - 1];
#pragma unroll
    for (int i = 0; i < PER; i++) {
        int idx = base + i;
        if (idx <= NN) g_rowptr[idx] = excl + loc[i];
    }
    __syncthreads();
    for (int i = tid; i < NN; i += TPB) g_cursor[i] = g_rowptr[i];
}

// gate-interleave permutation: plane row j -> torch row
__device__ __forceinline__ int gate_perm(int j) {
    return ((j >> 3) & 3) * 64 + (j >> 5) * 8 + (j & 7);
}

#define FILL_BLOCKS ((EE + 255) / 256)
#define PREP_BLOCKS ((PREP_ELEMS + 255) / 256)
#define XCONV_BLOCKS ((MROWS * FIN) / (256 * 4))   // 2500
__global__ void k_fillprep(const int* __restrict__ src, const int* __restrict__ dst,
                           const float* __restrict__ xin,
                           const float* __restrict__ wg0, const float* __restrict__ wg1,
                           const float* __restrict__ wg2,
                           const float* __restrict__ wih0, const float* __restrict__ wih1,
                           const float* __restrict__ wih2,
                           const float* __restrict__ whh0, const float* __restrict__ whh1,
                           const float* __restrict__ whh2,
                           const float* __restrict__ bih0, const float* __restrict__ bhh0,
                           const float* __restrict__ bih1, const float* __restrict__ bhh1,
                           const float* __restrict__ bih2, const float* __restrict__ bhh2) {
    int b = blockIdx.x;
    int tid = threadIdx.x;
    if (b < FILL_BLOCKS) {
        int e = b * 256 + tid;
        if (e < EE) {
            int s = src[e], d = dst[e];
            int p = atomicAdd(&g_cursor[d], 1);
            g_csr_src[p]  = s;
            g_csr_coef[p] = g_dis[s] * g_dis[d];
        }
        return;
    }
    if (b < FILL_BLOCKS + PREP_BLOCKS) {
        int idx = (b - FILL_BLOCKS) * 256 + tid;
        if (idx >= PREP_ELEMS) return;
        if (idx < WTOT) {
            float v;
            if (idx < WO1)       { int r = idx - WO0; v = wg0[(r & 31)  * HID + (r >> 5)]; }
            else if (idx < WO2)  { int r = idx - WO1; v = wg1[(r & 127) * HID + (r >> 7)]; }
            else if (idx < WO3)  { int r = idx - WO2; v = wg2[(r & 127) * HID + (r >> 7)]; }
            else if (idx < WO4)  { int l = idx - WO3; v = wih0[gate_perm(l >> 7) * 128 + (l & 127)]; }
            else if (idx < WO5)  { int l = idx - WO4; v = wih1[gate_perm(l >> 6) * 64 + (l & 63)]; }
            else if (idx < WH0)  { int l = idx - WO5; v = wih2[gate_perm(l >> 6) * 64 + (l & 63)]; }
            else if (idx < WH1)  { int l = idx - WH0; v = whh0[gate_perm(l >> 6) * 64 + (l & 63)]; }
            else if (idx < WH2)  { int l = idx - WH1; v = whh1[gate_perm(l >> 6) * 64 + (l & 63)]; }
            else                 { int l = idx - WH2; v = whh2[gate_perm(l >> 6) * 64 + (l & 63)]; }
            g_wH[idx] = __float2half_rn(v);
        } else {
            int r = idx - WTOT;
            int l = r >> 8, j = r & 255;
            int orig = gate_perm(j);
            const float* a = (l == 0) ? bih0 : (l == 1) ? bih1 : bih2;
            const float* c = (l == 0) ? bhh0 : (l == 1) ? bhh1 : bhh2;
            g_biasc[r] = a[orig] + c[orig];
        }
        return;
    }
    // x -> fp16 conversion: 4 floats per thread
    int idx = (b - FILL_BLOCKS - PREP_BLOCKS) * 256 + tid;
    int base = idx * 4;
    if (base < MROWS * FIN) {
        float4 v = *(const float4*)(xin + base);
        uint2 o = make_uint2(pack_h2(v.x, v.y), pack_h2(v.z, v.w));
        *(uint2*)(g_xH + base) = o;
    }
}

// ===================== fused agg + GEMM =====================================
// C = (Â prev) @ W^T with epilogue. Block = 128 m-rows; the A tile is built
// in-smem by a warp-per-row gather-reduce from prev (fp32 accum -> fp16),
// while W chunks stream in via cp.async. Then a fully-resident MMA.
// mode: 1 = relu(.+bias) ; 2 = bn(relu(.+bias))
template <int K>
__global__ void __launch_bounds__(256, 2)
k_agg_gemm(const __half* __restrict__ prev, const __half* __restrict__ W,
           const float* __restrict__ bias,
           const float* __restrict__ bng, const float* __restrict__ bnb,
           const float* __restrict__ bnm, const float* __restrict__ bnv,
           int mode, __half* __restrict__ outH) {
    constexpr int KC  = 32;
    constexpr int NCH = K / KC;
    constexpr int P2  = 80;             // bytes per 32-k chunk row (40 halfs)
    constexpr int S   = 128 * P2;       // 10240 per chunk plane
    extern __shared__ char sm[];
    uint32_t sA = smem_u32(sm);         // A planes: NCH * S
    uint32_t sW = sA + NCH * S;         // W planes: NCH * S

    int tid = threadIdx.x, wid = tid >> 5, lane = tid & 31;
    int wm = wid & 1, wn = wid >> 1;
    int mBase = blockIdx.x * 128;

    // ---- stage all W chunks (background) ----
    for (int idx = tid; idx < NCH * 512; idx += 256) {
        int ch = idx >> 9, rem = idx & 511;
        int row = rem >> 2, c = rem & 3;
        cp16(sW + ch * S + row * P2 + c * 16, W + (size_t)row * K + ch * KC + c * 8);
    }
    cp_commit();

    // ---- gather-reduce A rows into smem (warp per row, 16 rows/warp) ----
    for (int rr = 0; rr < 16; rr++) {
        int r = wid * 16 + rr;
        int m = mBase + r;
        int t = m / NN, n = m - t * NN;
        int p0 = g_rowptr[n], p1 = g_rowptr[n + 1];
        float dv = g_dis[n];
        float swc = dv * dv;
        const __half* basep = prev + (size_t)t * NN * K;
        if (K == 128) {
            int c0 = lane * 4;
            float a0 = 0.f, a1 = 0.f, a2 = 0.f, a3 = 0.f;
            float b0 = 0.f, b1 = 0.f, b2 = 0.f, b3 = 0.f;
            int p = p0;
            for (; p + 1 < p1; p += 2) {
                int s0 = g_csr_src[p];     float cf0 = g_csr_coef[p];
                int s1 = g_csr_src[p + 1]; float cf1 = g_csr_coef[p + 1];
                uint2 v0 = *(const uint2*)(basep + (size_t)s0 * K + c0);
                uint2 v1 = *(const uint2*)(basep + (size_t)s1 * K + c0);
                float2 x0 = __half22float2(*(__half2*)&v0.x);
                float2 y0 = __half22float2(*(__half2*)&v0.y);
                float2 x1 = __half22float2(*(__half2*)&v1.x);
                float2 y1 = __half22float2(*(__half2*)&v1.y);
                a0 += x0.x * cf0; a1 += x0.y * cf0; a2 += y0.x * cf0; a3 += y0.y * cf0;
                b0 += x1.x * cf1; b1 += x1.y * cf1; b2 += y1.x * cf1; b3 += y1.y * cf1;
            }
            if (p < p1) {
                int s0 = g_csr_src[p]; float cf0 = g_csr_coef[p];
                uint2 v0 = *(const uint2*)(basep + (size_t)s0 * K + c0);
                float2 x0 = __half22float2(*(__half2*)&v0.x);
                float2 y0 = __half22float2(*(__half2*)&v0.y);
                a0 += x0.x * cf0; a1 += x0.y * cf0; a2 += y0.x * cf0; a3 += y0.y * cf0;
            }
            uint2 hv = *(const uint2*)(basep + (size_t)n * K + c0);
            float2 hx = __half22float2(*(__half2*)&hv.x);
            float2 hy = __half22float2(*(__half2*)&hv.y);
            a0 += b0 + hx.x * swc; a1 += b1 + hx.y * swc;
            a2 += b2 + hy.x * swc; a3 += b3 + hy.y * swc;
            uint2 o = make_uint2(pack_h2(a0, a1), pack_h2(a2, a3));
            *(uint2*)(sm + (c0 >> 5) * S + r * P2 + (c0 & 31) * 2) = o;
        } else {  // K == 32
            float a0 = 0.f, b0 = 0.f;
            int p = p0;
            for (; p + 1 < p1; p += 2) {
                int s0 = g_csr_src[p];     float cf0 = g_csr_coef[p];
                int s1 = g_csr_src[p + 1]; float cf1 = g_csr_coef[p + 1];
                a0 += __half2float(basep[(size_t)s0 * K + lane]) * cf0;
                b0 += __half2float(basep[(size_t)s1 * K + lane]) * cf1;
            }
            if (p < p1)
                a0 += __half2float(basep[(size_t)g_csr_src[p] * K + lane]) * g_csr_coef[p];
            a0 += b0 + __half2float(basep[(size_t)n * K + lane]) * swc;
            *(__half*)(sm + r * P2 + lane * 2) = __float2half_rn(a0);
        }
    }
    cp_wait0();
    __syncthreads();

    // ---- MMA (all chunks resident) ----
    float acc[4][4][4];
#pragma unroll
    for (int i = 0; i < 4; i++)
#pragma unroll
        for (int j = 0; j < 4; j++)
#pragma unroll
            for (int r = 0; r < 4; r++) acc[i][j][r] = 0.0f;

    uint32_t aOff = (uint32_t)((wm * 64 + (lane & 15)) * P2 + (lane >> 4) * 16);
    uint32_t bOff = (uint32_t)((wn * 32 + (lane & 7) + ((lane >> 4) << 3)) * P2 +
                               ((lane >> 3) & 1) * 16);

#pragma unroll
    for (int ch = 0; ch < NCH; ch++) {
#pragma unroll
        for (int ks = 0; ks < 2; ks++) {
            uint32_t ka = ks * 32;
            uint32_t bh[2][4];
#pragma unroll
            for (int j2 = 0; j2 < 2; j2++)
                ldsm_x4(bh[j2], sW + ch * S + bOff + j2 * (16 * P2) + ka);
#pragma unroll
            for (int i = 0; i < 4; i++) {
                uint32_t ah[4];
                ldsm_x4(ah, sA + ch * S + aOff + i * (16 * P2) + ka);
#pragma unroll
                for (int j = 0; j < 4; j++)
                    mma16816(acc[i][j], ah, &bh[j >> 1][(j & 1) * 2]);
            }
        }
    }

    // ---- epilogue ----
    float pb[4][2], psc[4][2], pmn[4][2], pbb[4][2];
#pragma unroll
    for (int j = 0; j < 4; j++) {
        int c = wn * 32 + j * 8 + (lane & 3) * 2;
#pragma unroll
        for (int q = 0; q < 2; q++) {
            pb[j][q] = bias[c + q];
            if (mode == 2) {
                psc[j][q] = bng[c + q] * rsqrtf(bnv[c + q] + EPSBN);
                pmn[j][q] = bnm[c + q];
                pbb[j][q] = bnb[c + q];
            }
        }
    }
#pragma unroll
    for (int i = 0; i < 4; i++) {
        int r0 = mBase + wm * 64 + i * 16 + (lane >> 2);
#pragma unroll
        for (int j = 0; j < 4; j++) {
            int c = wn * 32 + j * 8 + (lane & 3) * 2;
            float v[4];
#pragma unroll
            for (int r = 0; r < 4; r++) {
                float x = acc[i][j][r] + pb[j][r & 1];
                x = fmaxf(x, 0.0f);
                if (mode == 2) x = (x - pmn[j][r & 1]) * psc[j][r & 1] + pbb[j][r & 1];
                v[r] = x;
            }
            *(uint32_t*)(outH + (size_t)r0 * HID + c)       = pack_h2(v[0], v[1]);
            *(uint32_t*)(outH + (size_t)(r0 + 8) * HID + c) = pack_h2(v[2], v[3]);
        }
    }
}

// ===================== mma.sync fp16 GEMM (double-buffered, 2 CTA/SM) =======
// Used for LSTM layer-0 input projection only. mode 0 = +bias.
template <int K>
__global__ void __launch_bounds__(256, 2)
k_gemm_mma(const __half* __restrict__ A, const __half* __restrict__ W,
           const float* __restrict__ bias, int Nout, __half* __restrict__ outH) {
    constexpr int KC   = 32;
    constexpr int NCH  = K / KC;
    constexpr int NBUF = (NCH > 1) ? 2 : 1;
    constexpr int P2   = 80;
    constexpr int S    = 128 * P2;
    constexpr int BUF  = 2 * S;
    extern __shared__ char sm[];
    uint32_t sA = smem_u32(sm);

    int tid = threadIdx.x, wid = tid >> 5, lane = tid & 31;
    int wm = wid & 1, wn = wid >> 1;
    int mBase = blockIdx.x * 128;
    int jBase = blockIdx.y * 128;

    float acc[4][4][4];
#pragma unroll
    for (int i = 0; i < 4; i++)
#pragma unroll
        for (int j = 0; j < 4; j++)
#pragma unroll
            for (int r = 0; r < 4; r++) acc[i][j][r] = 0.0f;

    uint32_t aOff = (uint32_t)((wm * 64 + (lane & 15)) * P2 + (lane >> 4) * 16);
    uint32_t bOff = (uint32_t)((wn * 32 + (lane & 7) + ((lane >> 4) << 3)) * P2 +
                               ((lane >> 3) & 1) * 16);

    auto stage = [&](int ch) {
        uint32_t b = sA + (uint32_t)(ch % NBUF) * BUF;
#pragma unroll
        for (int s2 = 0; s2 < 2; s2++) {
            int idx = tid + s2 * 256;
            int row = idx >> 2, c = idx & 3;
            uint32_t d = b + row * P2 + c * 16;
            size_t ga = (size_t)(mBase + row) * K + ch * KC + c * 8;
            size_t gw = (size_t)(jBase + row) * K + ch * KC + c * 8;
            cp16(d,     A + ga);
            cp16(d + S, W + gw);
        }
        cp_commit();
    };

    stage(0);
#pragma unroll
    for (int ch = 0; ch < NCH; ch++) {
        if (ch + 1 < NCH) { stage(ch + 1); cp_wait1(); } else { cp_wait0(); }
        __syncthreads();
        uint32_t b = sA + (uint32_t)(ch % NBUF) * BUF;
#pragma unroll
        for (int ks = 0; ks < 2; ks++) {
            uint32_t ka = ks * 32;
            uint32_t bh[2][4];
#pragma unroll
            for (int j2 = 0; j2 < 2; j2++)
                ldsm_x4(bh[j2], b + S + bOff + j2 * (16 * P2) + ka);
#pragma unroll
            for (int i = 0; i < 4; i++) {
                uint32_t ah[4];
                ldsm_x4(ah, b + aOff + i * (16 * P2) + ka);
#pragma unroll
                for (int j = 0; j < 4; j++)
                    mma16816(acc[i][j], ah, &bh[j >> 1][(j & 1) * 2]);
            }
        }
        if (ch + 1 < NCH) __syncthreads();
    }

    float pb[4][2];
#pragma unroll
    for (int j = 0; j < 4; j++) {
        int c = jBase + wn * 32 + j * 8 + (lane & 3) * 2;
        pb[j][0] = bias[c];
        pb[j][1] = bias[c + 1];
    }
#pragma unroll
    for (int i = 0; i < 4; i++) {
        int r0 = mBase + wm * 64 + i * 16 + (lane >> 2);
#pragma unroll
        for (int j = 0; j < 4; j++) {
            int c = jBase + wn * 32 + j * 8 + (lane & 3) * 2;
            float v[4];
#pragma unroll
            for (int r = 0; r < 4; r++) v[r] = acc[i][j][r] + pb[j][r & 1];
            *(uint32_t*)(outH + (size_t)r0 * Nout + c)       = pack_h2(v[0], v[1]);
            *(uint32_t*)(outH + (size_t)(r0 + 8) * Nout + c) = pack_h2(v[2], v[3]);
        }
    }
}

// ===================== tensor-core LSTM layer 0 (pre from GEMM) =============
#define LP2 144                 // 72 halfs pitch
#define S_WHH 0
#define S_H   36864
#define LSTM_MMA_SMEM 46080

__global__ void __launch_bounds__(256, 2)
k_lstm_mma(const __half* __restrict__ pre, const __half* __restrict__ whh,
           __half* __restrict__ yH) {
    extern __shared__ char sm[];
    uint32_t sA = smem_u32(sm);
    int tid = threadIdx.x, wid = tid >> 5, lane = tid & 31;
    int wm = wid & 1, wn = wid >> 1;
    int nodeBase = blockIdx.x * 64;

    for (int idx = tid; idx < 2048; idx += 256) {
        int r = idx >> 3, c = idx & 7;
        cp16(sA + S_WHH + r * LP2 + c * 16, whh + r * 64 + c * 8);
    }
    for (int idx = tid; idx < 2304; idx += 256)
        ((uint32_t*)(sm + S_H))[idx] = 0;
    cp_commit(); cp_wait0();
    __syncthreads();

    uint32_t aOff = (uint32_t)((wm * 32 + (lane & 15)) * LP2 + (lane >> 4) * 16);
    uint32_t bOff = (uint32_t)((wn * 64 + (lane & 7) + ((lane >> 4) << 3)) * LP2 +
                               ((lane >> 3) & 1) * 16);
    float cst[16];
#pragma unroll
    for (int w = 0; w < 16; w++) cst[w] = 0.0f;

    for (int t = 0; t < T_STEPS; t++) {
        float acc[2][8][4];
#pragma unroll
        for (int i = 0; i < 2; i++)
#pragma unroll
            for (int j = 0; j < 8; j++)
#pragma unroll
                for (int r = 0; r < 4; r++) acc[i][j][r] = 0.0f;

#pragma unroll
        for (int ks = 0; ks < 4; ks++) {
            uint32_t ka = ks * 32;
            uint32_t bh[4][4];
#pragma unroll
            for (int j2 = 0; j2 < 4; j2++)
                ldsm_x4(bh[j2], sA + S_WHH + bOff + j2 * (16 * LP2) + ka);
#pragma unroll
            for (int i = 0; i < 2; i++) {
                uint32_t ah[4];
                ldsm_x4(ah, sA + S_H + aOff + i * (16 * LP2) + ka);
#pragma unroll
                for (int j = 0; j < 8; j++)
                    mma16816(acc[i][j], ah, &bh[j >> 1][(j & 1) * 2]);
            }
        }
        __syncthreads();

#pragma unroll
        for (int i = 0; i < 2; i++) {
            int rbase = wm * 32 + i * 16 + (lane >> 2);
#pragma unroll
            for (int rr = 0; rr < 2; rr++) {
                int row = rbase + rr * 8;
                int n = nodeBase + row;
                bool valid = n < NN;
                const __half* pp = pre + ((size_t)t * NN + n) * G4;
#pragma unroll
                for (int gl = 0; gl < 2; gl++) {
                    int cb = wn * 64 + gl * 32 + (lane & 3) * 2;
                    float2 p0 = make_float2(0.f, 0.f), p1 = p0, p2 = p0, p3 = p0;
                    if (valid) {
                        p0 = __half22float2(*(const __half2*)(pp + cb));
                        p1 = __half22float2(*(const __half2*)(pp + cb + 8));
                        p2 = __half22float2(*(const __half2*)(pp + cb + 16));
                        p3 = __half22float2(*(const __half2*)(pp + cb + 24));
                    }
                    float hn2[2];
#pragma unroll
                    for (int vv = 0; vv < 2; vv++) {
                        int w = i * 8 + rr * 4 + gl * 2 + vv;
                        float gi = acc[i][gl * 4 + 0][rr * 2 + vv] + (vv ? p0.y : p0.x);
                        float gf = acc[i][gl * 4 + 1][rr * 2 + vv] + (vv ? p1.y : p1.x);
                        float gg = acc[i][gl * 4 + 2][rr * 2 + vv] + (vv ? p2.y : p2.x);
                        float go = acc[i][gl * 4 + 3][rr * 2 + vv] + (vv ? p3.y : p3.x);
                        float ig = sigmoidf_(gi);
                        float fg = sigmoidf_(gf);
                        float gt = tanhf_(gg);
                        float og = sigmoidf_(go);
                        float cn = fg * cst[w] + ig * gt;
                        cst[w] = cn;
                        hn2[vv] = og * tanhf_(cn);
                    }
                    int u = (wn * 2 + gl) * 8 + (lane & 3) * 2;
                    uint32_t hi2 = pack_h2(hn2[0], hn2[1]);
                    *(uint32_t*)(sm + S_H + row * LP2 + u * 2) = hi2;
                    if (valid) {
                        size_t o = ((size_t)t * NN + n) * OUTD + u;
                        *(uint32_t*)(yH + o) = hi2;
                    }
                }
            }
        }
        __syncthreads();
    }
}

// ===================== fused LSTM layers 1/2 (input projection in-kernel) ===
#define F_WIH  0
#define F_WHH  36864
#define F_H    73728            // 9216
#define F_X    82944            // 2 x 9216
#define F_BIAS 101376           // 1024
#define LSTM_FUSED_SMEM 102400

__global__ void __launch_bounds__(256, 2)
k_lstm_fused(const __half* __restrict__ xin,
             const __half* __restrict__ wih, const __half* __restrict__ whh,
             const float* __restrict__ bias,
             __half* __restrict__ yH, float* __restrict__ outFinal) {
    extern __shared__ char sm[];
    uint32_t sA = smem_u32(sm);
    int tid = threadIdx.x, wid = tid >> 5, lane = tid & 31;
    int wm = wid & 1, wn = wid >> 1;
    int nodeBase = blockIdx.x * 64;

    for (int idx = tid; idx < 2048; idx += 256) {
        int r = idx >> 3, c = idx & 7;
        cp16(sA + F_WIH + r * LP2 + c * 16, wih + r * 64 + c * 8);
        cp16(sA + F_WHH + r * LP2 + c * 16, whh + r * 64 + c * 8);
    }
    ((float*)(sm + F_BIAS))[tid] = bias[tid];
    for (int idx = tid; idx < 2304; idx += 256)
        ((uint32_t*)(sm + F_H))[idx] = 0;

    auto stage_x = [&](int t) {
        uint32_t b = sA + F_X + (uint32_t)(t & 1) * 9216;
#pragma unroll
        for (int s2 = 0; s2 < 2; s2++) {
            int idx = tid + s2 * 256;
            int r = idx >> 3, c = idx & 7;
            int n = nodeBase + r;
            if (n >= NN) n = NN - 1;
            cp16(b + r * LP2 + c * 16, xin + ((size_t)t * NN + n) * OUTD + c * 8);
        }
    };
    stage_x(0);
    cp_commit();

    uint32_t aOff = (uint32_t)((wm * 32 + (lane & 15)) * LP2 + (lane >> 4) * 16);
    uint32_t bOff = (uint32_t)((wn * 64 + (lane & 7) + ((lane >> 4) << 3)) * LP2 +
                               ((lane >> 3) & 1) * 16);
    float cst[16];
#pragma unroll
    for (int w = 0; w < 16; w++) cst[w] = 0.0f;

    for (int t = 0; t < T_STEPS; t++) {
        if (t + 1 < T_STEPS) { stage_x(t + 1); cp_commit(); cp_wait1(); }
        else                 { cp_wait0(); }
        __syncthreads();

        float acc[2][8][4];
#pragma unroll
        for (int i = 0; i < 2; i++)
#pragma unroll
            for (int j = 0; j < 8; j++)
#pragma unroll
                for (int r = 0; r < 4; r++) acc[i][j][r] = 0.0f;

        uint32_t xb = sA + F_X + (uint32_t)(t & 1) * 9216;
#pragma unroll
        for (int ks = 0; ks < 4; ks++) {
            uint32_t ka = ks * 32;
            uint32_t bh[4][4];
#pragma unroll
            for (int j2 = 0; j2 < 4; j2++)
                ldsm_x4(bh[j2], sA + F_WIH + bOff + j2 * (16 * LP2) + ka);
#pragma unroll
            for (int i = 0; i < 2; i++) {
                uint32_t ah[4];
                ldsm_x4(ah, xb + aOff + i * (16 * LP2) + ka);
#pragma unroll
                for (int j = 0; j < 8; j++)
                    mma16816(acc[i][j], ah, &bh[j >> 1][(j & 1) * 2]);
            }
        }
#pragma unroll
        for (int ks = 0; ks < 4; ks++) {
            uint32_t ka = ks * 32;
            uint32_t bh[4][4];
#pragma unroll
            for (int j2 = 0; j2 < 4; j2++)
                ldsm_x4(bh[j2], sA + F_WHH + bOff + j2 * (16 * LP2) + ka);
#pragma unroll
            for (int i = 0; i < 2; i++) {
                uint32_t ah[4];
                ldsm_x4(ah, sA + F_H + aOff + i * (16 * LP2) + ka);
#pragma unroll
                for (int j = 0; j < 8; j++)
                    mma16816(acc[i][j], ah, &bh[j >> 1][(j & 1) * 2]);
            }
        }
        __syncthreads();

        const float* bsm = (const float*)(sm + F_BIAS);
#pragma unroll
        for (int i = 0; i < 2; i++) {
            int rbase = wm * 32 + i * 16 + (lane >> 2);
#pragma unroll
            for (int rr = 0; rr < 2; rr++) {
                int row = rbase + rr * 8;
                int n = nodeBase + row;
                bool valid = n < NN;
#pragma unroll
                for (int gl = 0; gl < 2; gl++) {
                    int cb = wn * 64 + gl * 32 + (lane & 3) * 2;
                    float2 b0 = *(const float2*)(bsm + cb);
                    float2 b1 = *(const float2*)(bsm + cb + 8);
                    float2 b2 = *(const float2*)(bsm + cb + 16);
                    float2 b3 = *(const float2*)(bsm + cb + 24);
                    float hn2[2];
#pragma unroll
                    for (int vv = 0; vv < 2; vv++) {
                        int w = i * 8 + rr * 4 + gl * 2 + vv;
                        float gi = acc[i][gl * 4 + 0][rr * 2 + vv] + (vv ? b0.y : b0.x);
                        float gf = acc[i][gl * 4 + 1][rr * 2 + vv] + (vv ? b1.y : b1.x);
                        float gg = acc[i][gl * 4 + 2][rr * 2 + vv] + (vv ? b2.y : b2.x);
                        float go = acc[i][gl * 4 + 3][rr * 2 + vv] + (vv ? b3.y : b3.x);
                        float ig = sigmoidf_(gi);
                        float fg = sigmoidf_(gf);
                        float gt = tanhf_(gg);
                        float og = sigmoidf_(go);
                        float cn = fg * cst[w] + ig * gt;
                        cst[w] = cn;
                        hn2[vv] = og * tanhf_(cn);
                    }
                    int u = (wn * 2 + gl) * 8 + (lane & 3) * 2;
                    uint32_t hi2 = pack_h2(hn2[0], hn2[1]);
                    *(uint32_t*)(sm + F_H + row * LP2 + u * 2) = hi2;
                    if (valid) {
                        if (yH) {
                            size_t o = ((size_t)t * NN + n) * OUTD + u;
                            *(uint32_t*)(yH + o) = hi2;
                        }
                        if (outFinal && t == T_STEPS - 1)
                            *(float2*)(outFinal + (size_t)n * OUTD + u) =
                                make_float2(hn2[0], hn2[1]);
                    }
                }
            }
        }
        __syncthreads();
    }
}

// ===================== host =====================
extern "C" void kernel_launch(void* const* d_in, const int* in_sizes, int n_in,
                              void* d_out, int out_size) {
    const float* x   = (const float*)d_in[0];
    const int*   ei  = (const int*)d_in[1];
    const int*   src = ei;
    const int*   dst = ei + EE;
    const float* wg[3] = {(const float*)d_in[2], (const float*)d_in[4], (const float*)d_in[6]};
    const float* bg[3] = {(const float*)d_in[3], (const float*)d_in[5], (const float*)d_in[7]};
    const float* bnG[2] = {(const float*)d_in[8],  (const float*)d_in[12]};
    const float* bnB[2] = {(const float*)d_in[9],  (const float*)d_in[13]};
    const float* bnM[2] = {(const float*)d_in[10], (const float*)d_in[14]};
    const float* bnV[2] = {(const float*)d_in[11], (const float*)d_in[15]};
    const float* wih[3] = {(const float*)d_in[16], (const float*)d_in[20], (const float*)d_in[24]};
    const float* whh[3] = {(const float*)d_in[17], (const float*)d_in[21], (const float*)d_in[25]};
    const float* bih[3] = {(const float*)d_in[18], (const float*)d_in[22], (const float*)d_in[26]};
    const float* bhh[3] = {(const float*)d_in[19], (const float*)d_in[23], (const float*)d_in[27]};
    float* out = (float*)d_out;

    float* p_bias;
    __half *p_preH, *p_xH, *p_actA, *p_actB, *p_yA, *p_yB, *p_wH;
    cudaGetSymbolAddress((void**)&p_preH, g_preH);
    cudaGetSymbolAddress((void**)&p_xH,   g_xH);
    cudaGetSymbolAddress((void**)&p_bias, g_biasc);
    cudaGetSymbolAddress((void**)&p_actA, g_actA);
    cudaGetSymbolAddress((void**)&p_actB, g_actB);
    cudaGetSymbolAddress((void**)&p_yA,   g_yA);
    cudaGetSymbolAddress((void**)&p_yB,   g_yB);
    cudaGetSymbolAddress((void**)&p_wH,   g_wH);

    const int AG32  = 2 * 10240;   // K=32 fused agg-gemm
    const int AG128 = 8 * 10240;   // K=128 fused agg-gemm
    const int SM2   = 40960;       // pre-GEMM double buffer
    cudaFuncSetAttribute(k_agg_gemm<32>,  cudaFuncAttributeMaxDynamicSharedMemorySize, AG32);
    cudaFuncSetAttribute(k_agg_gemm<128>, cudaFuncAttributeMaxDynamicSharedMemorySize, AG128);
    cudaFuncSetAttribute(k_gemm_mma<128>, cudaFuncAttributeMaxDynamicSharedMemorySize, SM2);
    cudaFuncSetAttribute(k_lstm_mma,   cudaFuncAttributeMaxDynamicSharedMemorySize, LSTM_MMA_SMEM);
    cudaFuncSetAttribute(k_lstm_fused, cudaFuncAttributeMaxDynamicSharedMemorySize, LSTM_FUSED_SMEM);

    // ---- setup ----
    k_zero_cnt<<<(NN + 255) / 256, 256>>>();
    k_hist<<<(EE + 255) / 256, 256>>>(dst);
    k_scanfused<<<1, 1024>>>();
    k_fillprep<<<FILL_BLOCKS + PREP_BLOCKS + XCONV_BLOCKS, 256>>>(
        src, dst, x, wg[0], wg[1], wg[2], wih[0], wih[1], wih[2],
        whh[0], whh[1], whh[2],
        bih[0], bhh[0], bih[1], bhh[1], bih[2], bhh[2]);

    const int MT = MROWS / 128;  // 625 M tiles

    // ---- GCN layers (agg fused into GEMM) ----
    k_agg_gemm<32><<<MT, 256, AG32>>>(
        p_xH, p_wH + WO0, bg[0], bnG[0], bnB[0], bnM[0], bnV[0], 2, p_actB);
    k_agg_gemm<128><<<MT, 256, AG128>>>(
        p_actB, p_wH + WO1, bg[1], bnG[1], bnB[1], bnM[1], bnV[1], 2, p_actA);
    k_agg_gemm<128><<<MT, 256, AG128>>>(
        p_actA, p_wH + WO2, bg[2], nullptr, nullptr, nullptr, nullptr, 1, p_actB);

    int lstmBlocks = (NN + 63) / 64;  // 157
    // ---- LSTM layer 0 (input GEMM + recurrence) ----
    k_gemm_mma<128><<<dim3(MT, 2), 256, SM2>>>(
        p_actB, p_wH + WO3, p_bias + 0 * G4, G4, p_preH);
    k_lstm_mma<<<lstmBlocks, 256, LSTM_MMA_SMEM>>>(p_preH, p_wH + WH0, p_yA);
    // ---- LSTM layers 1 & 2 (fully fused) ----
    k_lstm_fused<<<lstmBlocks, 256, LSTM_FUSED_SMEM>>>(
        p_yA, p_wH + WO4, p_wH + WH1, p_bias + 1 * G4, p_yB, nullptr);
    k_lstm_fused<<<lstmBlocks, 256, LSTM_FUSED_SMEM>>>(
        p_yB, p_wH + WO5, p_wH + WH2, p_bias + 2 * G4, nullptr, out);
}

// round 14
// speedup vs baseline: 1.4125x; 1.4125x over previous
#include <cuda_runtime.h>
#include <cuda_fp16.h>
#include <math.h>
#include <stdint.h>

#define T_STEPS 8
#define NN      10000
#define EE      200000
#define FIN     32
#define HID     128
#define OUTD    64
#define G4      256            // 4*OUT
#define MROWS   (T_STEPS*NN)   // 80000
#define EPSBN   1e-5f

// weight-plane offsets ([n][k] fp16 layout, packed)
// LSTM planes (WO3.., WH..) use gate-interleaved row permutation:
//   plane row j = g*32 + q*8 + v  <->  torch row = q*64 + g*8 + v
#define WO0 0            // wg0^T   128x32
#define WO1 4096         // wg1^T   128x128
#define WO2 20480        // wg2^T   128x128
#define WO3 36864        // w_ih0   256x128 (perm)
#define WO4 69632        // w_ih1   256x64  (perm)
#define WO5 86016        // w_ih2   256x64  (perm)
#define WH0 102400       // whh0    256x64  (perm)
#define WH1 118784       // whh1    256x64  (perm)
#define WH2 135168       // whh2    256x64  (perm)
#define WTOT 151552
#define PREP_ELEMS (WTOT + 768)

// ===================== scratch (device globals) =====================
static __device__ __half g_preH[MROWS*G4];     // LSTM0 input projections (fp16, permuted)
static __device__ __half g_xH  [MROWS*FIN];    // x converted to fp16
static __device__ __half g_actA[MROWS*HID];    // ping
static __device__ __half g_actB[MROWS*HID];    // pong
static __device__ __half g_yA[MROWS*OUTD];
static __device__ __half g_yB[MROWS*OUTD];
static __device__ __half g_wH[WTOT];
static __device__ float g_biasc[3*G4];         // permuted
static __device__ float g_dis[NN];
static __device__ int   g_cnt[NN];
static __device__ int   g_rowptr[NN+1];
static __device__ int   g_cursor[NN];
static __device__ int   g_csr_src[EE];
static __device__ float g_csr_coef[EE];

// ===================== helpers =====================
__device__ __forceinline__ uint32_t smem_u32(const void* p) {
    uint32_t a;
    asm("{ .reg .u64 t; cvta.to.shared.u64 t, %1; cvt.u32.u64 %0, t; }" : "=r"(a) : "l"(p));
    return a;
}
__device__ __forceinline__ void cp16(uint32_t s, const void* g) {
    asm volatile("cp.async.cg.shared.global [%0], [%1], 16;" :: "r"(s), "l"(g));
}
__device__ __forceinline__ void cp_commit() {
    asm volatile("cp.async.commit_group;");
}
__device__ __forceinline__ void cp_wait0() {
    asm volatile("cp.async.wait_group 0;");
}
__device__ __forceinline__ void cp_wait1() {
    asm volatile("cp.async.wait_group 1;");
}
__device__ __forceinline__ void ldsm_x4(uint32_t* r, uint32_t addr) {
    asm volatile("ldmatrix.sync.aligned.m8n8.x4.shared.b16 {%0,%1,%2,%3}, [%4];"
                 : "=r"(r[0]), "=r"(r[1]), "=r"(r[2]), "=r"(r[3]) : "r"(addr));
}
__device__ __forceinline__ void mma16816(float* d, const uint32_t* a, const uint32_t* b) {
    asm volatile(
        "mma.sync.aligned.m16n8k16.row.col.f32.f16.f16.f32 "
        "{%0,%1,%2,%3}, {%4,%5,%6,%7}, {%8,%9}, {%0,%1,%2,%3};"
        : "+f"(d[0]), "+f"(d[1]), "+f"(d[2]), "+f"(d[3])
        : "r"(a[0]), "r"(a[1]), "r"(a[2]), "r"(a[3]), "r"(b[0]), "r"(b[1]));
}
__device__ __forceinline__ uint32_t pack_h2(float x, float y) {
    __half2 h = __floats2half2_rn(x, y);
    return *(uint32_t*)&h;
}
__device__ __forceinline__ float sigmoidf_(float x) {
    return 1.0f / (1.0f + __expf(-x));
}
__device__ __forceinline__ float tanhf_(float x) {
    return 1.0f - 2.0f / (__expf(2.0f * x) + 1.0f);
}

// ===================== setup kernels =====================
__global__ void k_zero_cnt() {
    int i = blockIdx.x * blockDim.x + threadIdx.x;
    if (i < NN) g_cnt[i] = 0;
}
__global__ void k_hist(const int* __restrict__ dst) {
    int e = blockIdx.x * blockDim.x + threadIdx.x;
    if (e < EE) atomicAdd(&g_cnt[dst[e]], 1);
}
__global__ void k_scanfused() {
    const int TPB = 1024, PER = 10;
    __shared__ int sh[TPB];
    int tid = threadIdx.x;
    for (int i = tid; i < NN; i += TPB) g_dis[i] = rsqrtf((float)g_cnt[i] + 1.0f);
    int base = tid * PER;
    int loc[PER];
    int s = 0;
#pragma unroll
    for (int i = 0; i < PER; i++) {
        int idx = base + i;
        int v = (idx < NN) ? g_cnt[idx] : 0;
        loc[i] = s; s += v;
    }
    sh[tid] = s; __syncthreads();
    for (int off = 1; off < TPB; off <<= 1) {
        int v = (tid >= off) ? sh[tid - off] : 0;
        __syncthreads();
        sh[tid] += v;
        __syncthreads();
    }
    int excl = (tid == 0) ? 0 : sh[tid - 1];
#pragma unroll
    for (int i = 0; i < PER; i++) {
        int idx = base + i;
        if (idx <= NN) g_rowptr[idx] = excl + loc[i];
    }
    __syncthreads();
    for (int i = tid; i < NN; i += TPB) g_cursor[i] = g_rowptr[i];
}

// gate-interleave permutation: plane row j -> torch row
__device__ __forceinline__ int gate_perm(int j) {
    return ((j >> 3) & 3) * 64 + (j >> 5) * 8 + (j & 7);
}

#define FILL_BLOCKS ((EE + 255) / 256)
#define PREP_BLOCKS ((PREP_ELEMS + 255) / 256)
#define XCONV_BLOCKS ((MROWS * FIN) / (256 * 4))   // 2500
__global__ void k_fillprep(const int* __restrict__ src, const int* __restrict__ dst,
                           const float* __restrict__ xin,
                           const float* __restrict__ wg0, const float* __restrict__ wg1,
                           const float* __restrict__ wg2,
                           const float* __restrict__ wih0, const float* __restrict__ wih1,
                           const float* __restrict__ wih2,
                           const float* __restrict__ whh0, const float* __restrict__ whh1,
                           const float* __restrict__ whh2,
                           const float* __restrict__ bih0, const float* __restrict__ bhh0,
                           const float* __restrict__ bih1, const float* __restrict__ bhh1,
                           const float* __restrict__ bih2, const float* __restrict__ bhh2) {
    int b = blockIdx.x;
    int tid = threadIdx.x;
    if (b < FILL_BLOCKS) {
        int e = b * 256 + tid;
        if (e < EE) {
            int s = src[e], d = dst[e];
            int p = atomicAdd(&g_cursor[d], 1);
            g_csr_src[p]  = s;
            g_csr_coef[p] = g_dis[s] * g_dis[d];
        }
        return;
    }
    if (b < FILL_BLOCKS + PREP_BLOCKS) {
        int idx = (b - FILL_BLOCKS) * 256 + tid;
        if (idx >= PREP_ELEMS) return;
        if (idx < WTOT) {
            float v;
            if (idx < WO1)       { int r = idx - WO0; v = wg0[(r & 31)  * HID + (r >> 5)]; }
            else if (idx < WO2)  { int r = idx - WO1; v = wg1[(r & 127) * HID + (r >> 7)]; }
            else if (idx < WO3)  { int r = idx - WO2; v = wg2[(r & 127) * HID + (r >> 7)]; }
            else if (idx < WO4)  { int l = idx - WO3; v = wih0[gate_perm(l >> 7) * 128 + (l & 127)]; }
            else if (idx < WO5)  { int l = idx - WO4; v = wih1[gate_perm(l >> 6) * 64 + (l & 63)]; }
            else if (idx < WH0)  { int l = idx - WO5; v = wih2[gate_perm(l >> 6) * 64 + (l & 63)]; }
            else if (idx < WH1)  { int l = idx - WH0; v = whh0[gate_perm(l >> 6) * 64 + (l & 63)]; }
            else if (idx < WH2)  { int l = idx - WH1; v = whh1[gate_perm(l >> 6) * 64 + (l & 63)]; }
            else                 { int l = idx - WH2; v = whh2[gate_perm(l >> 6) * 64 + (l & 63)]; }
            g_wH[idx] = __float2half_rn(v);
        } else {
            int r = idx - WTOT;
            int l = r >> 8, j = r & 255;
            int orig = gate_perm(j);
            const float* a = (l == 0) ? bih0 : (l == 1) ? bih1 : bih2;
            const float* c = (l == 0) ? bhh0 : (l == 1) ? bhh1 : bhh2;
            g_biasc[r] = a[orig] + c[orig];
        }
        return;
    }
    int idx = (b - FILL_BLOCKS - PREP_BLOCKS) * 256 + tid;
    int base = idx * 4;
    if (base < MROWS * FIN) {
        float4 v = *(const float4*)(xin + base);
        uint2 o = make_uint2(pack_h2(v.x, v.y), pack_h2(v.z, v.w));
        *(uint2*)(g_xH + base) = o;
    }
}

// ===================== GCN aggregation =====================
__global__ void k_agg32(const __half* __restrict__ in, __half* __restrict__ oH) {
    int n = blockIdx.x;
    int t = threadIdx.x >> 5;
    int lane = threadIdx.x & 31;
    int p0 = g_rowptr[n], p1 = g_rowptr[n + 1];
    float d = g_dis[n];
    float sw = d * d;
    size_t m = (size_t)t * NN + n;
    float acc = 0.0f;
    for (int p = p0; p < p1; p++) {
        int s = g_csr_src[p];
        acc += __half2float(in[((size_t)t * NN + s) * FIN + lane]) * g_csr_coef[p];
    }
    float r = acc + __half2float(in[m * FIN + lane]) * sw;
    oH[m * FIN + lane] = __float2half_rn(r);
}

__global__ void k_aggh(const __half* __restrict__ in, __half* __restrict__ oH) {
    int n = blockIdx.x;
    int t = threadIdx.x >> 5;
    int lane = threadIdx.x & 31;
    int p0 = g_rowptr[n], p1 = g_rowptr[n + 1];
    float d = g_dis[n];
    float sw = d * d;
    size_t m = (size_t)t * NN + n;
    int c0 = lane * 4;
    float acc0 = 0.f, acc1 = 0.f, acc2 = 0.f, acc3 = 0.f;
    for (int p = p0; p < p1; p++) {
        int s = g_csr_src[p];
        float cf = g_csr_coef[p];
        uint2 v = *(const uint2*)(in + ((size_t)t * NN + s) * HID + c0);
        float2 a = __half22float2(*(__half2*)&v.x);
        float2 b = __half22float2(*(__half2*)&v.y);
        acc0 += a.x * cf; acc1 += a.y * cf;
        acc2 += b.x * cf; acc3 += b.y * cf;
    }
    uint2 hv = *(const uint2*)(in + m * HID + c0);
    float2 ha = __half22float2(*(__half2*)&hv.x);
    float2 hb = __half22float2(*(__half2*)&hv.y);
    acc0 += ha.x * sw; acc1 += ha.y * sw;
    acc2 += hb.x * sw; acc3 += hb.y * sw;
    uint2 o = make_uint2(pack_h2(acc0, acc1), pack_h2(acc2, acc3));
    *(uint2*)(oH + m * HID + c0) = o;
}

// ===================== mma.sync fp16 GEMM (double-buffered, 2 CTA/SM) =======
// C = A @ W^T. A: fp16 [M][K]; W: fp16 [Nout][K]. Single MMA pass.
// mode: 0 = +bias ; 1 = relu(.+bias) ; 2 = bn(relu(.+bias))
template <int K>
__global__ void __launch_bounds__(256, 2)
k_gemm_mma(const __half* __restrict__ A, const __half* __restrict__ W,
           const float* __restrict__ bias,
           const float* __restrict__ bng, const float* __restrict__ bnb,
           const float* __restrict__ bnm, const float* __restrict__ bnv,
           int mode, int Nout, __half* __restrict__ outH) {
    constexpr int KC   = 32;
    constexpr int NCH  = K / KC;
    constexpr int NBUF = (NCH > 1) ? 2 : 1;
    constexpr int P    = KC + 8;           // 40 halfs
    constexpr int P2   = P * 2;            // 80 bytes
    constexpr int S    = 128 * P2;         // 10240 per plane
    constexpr int BUF  = 2 * S;            // 20480 per buffer
    extern __shared__ char sm[];
    uint32_t sA = smem_u32(sm);

    int tid = threadIdx.x, wid = tid >> 5, lane = tid & 31;
    int wm = wid & 1, wn = wid >> 1;
    int mBase = blockIdx.x * 128;
    int jBase = blockIdx.y * 128;

    float acc[4][4][4];
#pragma unroll
    for (int i = 0; i < 4; i++)
#pragma unroll
        for (int j = 0; j < 4; j++)
#pragma unroll
            for (int r = 0; r < 4; r++) acc[i][j][r] = 0.0f;

    uint32_t aOff = (uint32_t)((wm * 64 + (lane & 15)) * P2 + (lane >> 4) * 16);
    uint32_t bOff = (uint32_t)((wn * 32 + (lane & 7) + ((lane >> 4) << 3)) * P2 +
                               ((lane >> 3) & 1) * 16);

    auto stage = [&](int ch) {
        uint32_t b = sA + (uint32_t)(ch % NBUF) * BUF;
#pragma unroll
        for (int s2 = 0; s2 < 2; s2++) {
            int idx = tid + s2 * 256;
            int row = idx >> 2, c = idx & 3;
            uint32_t d = b + row * P2 + c * 16;
            size_t ga = (size_t)(mBase + row) * K + ch * KC + c * 8;
            size_t gw = (size_t)(jBase + row) * K + ch * KC + c * 8;
            cp16(d,     A + ga);
            cp16(d + S, W + gw);
        }
        cp_commit();
    };

    stage(0);
#pragma unroll
    for (int ch = 0; ch < NCH; ch++) {
        if (ch + 1 < NCH) { stage(ch + 1); cp_wait1(); } else { cp_wait0(); }
        __syncthreads();
        uint32_t b = sA + (uint32_t)(ch % NBUF) * BUF;
#pragma unroll
        for (int ks = 0; ks < KC / 16; ks++) {
            uint32_t ka = ks * 32;
            uint32_t bh[2][4];
#pragma unroll
            for (int j2 = 0; j2 < 2; j2++)
                ldsm_x4(bh[j2], b + S + bOff + j2 * (16 * P2) + ka);
#pragma unroll
            for (int i = 0; i < 4; i++) {
                uint32_t ah[4];
                ldsm_x4(ah, b + aOff + i * (16 * P2) + ka);
#pragma unroll
                for (int j = 0; j < 4; j++)
                    mma16816(acc[i][j], ah, &bh[j >> 1][(j & 1) * 2]);
            }
        }
        if (ch + 1 < NCH) __syncthreads();
    }

    float pb[4][2], psc[4][2], pmn[4][2], pbb[4][2];
#pragma unroll
    for (int j = 0; j < 4; j++) {
        int c = jBase + wn * 32 + j * 8 + (lane & 3) * 2;
#pragma unroll
        for (int q = 0; q < 2; q++) {
            pb[j][q] = bias ? bias[c + q] : 0.0f;
            if (mode == 2) {
                psc[j][q] = bng[c + q] * rsqrtf(bnv[c + q] + EPSBN);
                pmn[j][q] = bnm[c + q];
                pbb[j][q] = bnb[c + q];
            }
        }
    }
#pragma unroll
    for (int i = 0; i < 4; i++) {
        int r0 = mBase + wm * 64 + i * 16 + (lane >> 2);
#pragma unroll
        for (int j = 0; j < 4; j++) {
            int c = jBase + wn * 32 + j * 8 + (lane & 3) * 2;
            float v[4];
#pragma unroll
            for (int r = 0; r < 4; r++) {
                float x = acc[i][j][r] + pb[j][r & 1];
                if (mode >= 1) x = fmaxf(x, 0.0f);
                if (mode == 2) x = (x - pmn[j][r & 1]) * psc[j][r & 1] + pbb[j][r & 1];
                v[r] = x;
            }
            *(uint32_t*)(outH + (size_t)r0 * Nout + c)       = pack_h2(v[0], v[1]);
            *(uint32_t*)(outH + (size_t)(r0 + 8) * Nout + c) = pack_h2(v[2], v[3]);
        }
    }
}

// ===================== tensor-core LSTM layer 0 (32 nodes/block) ============
// Warp wn owns plane cols wn*32..+31 = all 4 gates of units wn*8..wn*8+7.
#define LP2 144                 // 72 halfs pitch
#define S_WHH 0
#define S_H   36864             // 32 * 144 = 4608
#define LSTM_MMA_SMEM 41472

__global__ void __launch_bounds__(256, 4)
k_lstm_mma(const __half* __restrict__ pre, const __half* __restrict__ whh,
           __half* __restrict__ yH) {
    extern __shared__ char sm[];
    uint32_t sA = smem_u32(sm);
    int tid = threadIdx.x, wid = tid >> 5, lane = tid & 31;
    int wn = wid;
    int nodeBase = blockIdx.x * 32;

    for (int idx = tid; idx < 2048; idx += 256) {
        int r = idx >> 3, c = idx & 7;
        cp16(sA + S_WHH + r * LP2 + c * 16, whh + r * 64 + c * 8);
    }
    for (int idx = tid; idx < 1152; idx += 256)
        ((uint32_t*)(sm + S_H))[idx] = 0;
    cp_commit(); cp_wait0();
    __syncthreads();

    uint32_t aOff = (uint32_t)((lane & 15) * LP2 + (lane >> 4) * 16);
    uint32_t bOff = (uint32_t)((wn * 32 + (lane & 7) + ((lane >> 4) << 3)) * LP2 +
                               ((lane >> 3) & 1) * 16);
    float cst[8];
#pragma unroll
    for (int w = 0; w < 8; w++) cst[w] = 0.0f;

    for (int t = 0; t < T_STEPS; t++) {
        float acc[2][4][4];
#pragma unroll
        for (int i = 0; i < 2; i++)
#pragma unroll
            for (int j = 0; j < 4; j++)
#pragma unroll
                for (int r = 0; r < 4; r++) acc[i][j][r] = 0.0f;

#pragma unroll
        for (int ks = 0; ks < 4; ks++) {
            uint32_t ka = ks * 32;
            uint32_t bh[2][4];
#pragma unroll
            for (int j2 = 0; j2 < 2; j2++)
                ldsm_x4(bh[j2], sA + S_WHH + bOff + j2 * (16 * LP2) + ka);
#pragma unroll
            for (int i = 0; i < 2; i++) {
                uint32_t ah[4];
                ldsm_x4(ah, sA + S_H + aOff + i * (16 * LP2) + ka);
#pragma unroll
                for (int j = 0; j < 4; j++)
                    mma16816(acc[i][j], ah, &bh[j >> 1][(j & 1) * 2]);
            }
        }
        __syncthreads();   // all warps done reading h plane

#pragma unroll
        for (int i = 0; i < 2; i++) {
#pragma unroll
            for (int rr = 0; rr < 2; rr++) {
                int row = i * 16 + rr * 8 + (lane >> 2);
                int n = nodeBase + row;
                bool valid = n < NN;
                const __half* pp = pre + ((size_t)t * NN + n) * G4;
                int cb = wn * 32 + (lane & 3) * 2;
                float2 p0 = make_float2(0.f, 0.f), p1 = p0, p2 = p0, p3 = p0;
                if (valid) {
                    p0 = __half22float2(*(const __half2*)(pp + cb));
                    p1 = __half22float2(*(const __half2*)(pp + cb + 8));
                    p2 = __half22float2(*(const __half2*)(pp + cb + 16));
                    p3 = __half22float2(*(const __half2*)(pp + cb + 24));
                }
                float hn2[2];
#pragma unroll
                for (int vv = 0; vv < 2; vv++) {
                    int w = i * 4 + rr * 2 + vv;
                    float gi = acc[i][0][rr * 2 + vv] + (vv ? p0.y : p0.x);
                    float gf = acc[i][1][rr * 2 + vv] + (vv ? p1.y : p1.x);
                    float gg = acc[i][2][rr * 2 + vv] + (vv ? p2.y : p2.x);
                    float go = acc[i][3][rr * 2 + vv] + (vv ? p3.y : p3.x);
                    float ig = sigmoidf_(gi);
                    float fg = sigmoidf_(gf);
                    float gt = tanhf_(gg);
                    float og = sigmoidf_(go);
                    float cn = fg * cst[w] + ig * gt;
                    cst[w] = cn;
                    hn2[vv] = og * tanhf_(cn);
                }
                int u = wn * 8 + (lane & 3) * 2;
                uint32_t hi2 = pack_h2(hn2[0], hn2[1]);
                *(uint32_t*)(sm + S_H + row * LP2 + u * 2) = hi2;
                if (valid) {
                    size_t o = ((size_t)t * NN + n) * OUTD + u;
                    *(uint32_t*)(yH + o) = hi2;
                }
            }
        }
        __syncthreads();
    }
}

// ===================== fused LSTM layers 1/2 (32 nodes/block) ===============
#define F_WIH  0
#define F_WHH  36864
#define F_H    73728            // 4608
#define F_X    78336            // 2 x 4608
#define F_BIAS 87552            // 1024
#define LSTM_FUSED_SMEM 88576

__global__ void __launch_bounds__(256, 2)
k_lstm_fused(const __half* __restrict__ xin,
             const __half* __restrict__ wih, const __half* __restrict__ whh,
             const float* __restrict__ bias,
             __half* __restrict__ yH, float* __restrict__ outFinal) {
    extern __shared__ char sm[];
    uint32_t sA = smem_u32(sm);
    int tid = threadIdx.x, wid = tid >> 5, lane = tid & 31;
    int wn = wid;
    int nodeBase = blockIdx.x * 32;

    for (int idx = tid; idx < 2048; idx += 256) {
        int r = idx >> 3, c = idx & 7;
        cp16(sA + F_WIH + r * LP2 + c * 16, wih + r * 64 + c * 8);
        cp16(sA + F_WHH + r * LP2 + c * 16, whh + r * 64 + c * 8);
    }
    ((float*)(sm + F_BIAS))[tid] = bias[tid];
    for (int idx = tid; idx < 1152; idx += 256)
        ((uint32_t*)(sm + F_H))[idx] = 0;

    auto stage_x = [&](int t) {
        uint32_t b = sA + F_X + (uint32_t)(t & 1) * 4608;
        int r = tid >> 3, c = tid & 7;          // 32 rows x 8 chunks = 256
        int n = nodeBase + r;
        if (n >= NN) n = NN - 1;                // clamp (masked later)
        cp16(b + r * LP2 + c * 16, xin + ((size_t)t * NN + n) * OUTD + c * 8);
    };
    stage_x(0);
    cp_commit();

    uint32_t aOff = (uint32_t)((lane & 15) * LP2 + (lane >> 4) * 16);
    uint32_t bOff = (uint32_t)((wn * 32 + (lane & 7) + ((lane >> 4) << 3)) * LP2 +
                               ((lane >> 3) & 1) * 16);
    float cst[8];
#pragma unroll
    for (int w = 0; w < 8; w++) cst[w] = 0.0f;

    for (int t = 0; t < T_STEPS; t++) {
        if (t + 1 < T_STEPS) { stage_x(t + 1); cp_commit(); cp_wait1(); }
        else                 { cp_wait0(); }
        __syncthreads();   // x[t] ready; prev-step h writes visible

        float acc[2][4][4];
#pragma unroll
        for (int i = 0; i < 2; i++)
#pragma unroll
            for (int j = 0; j < 4; j++)
#pragma unroll
                for (int r = 0; r < 4; r++) acc[i][j][r] = 0.0f;

        // pass 1: x_t @ Wih^T
        uint32_t xb = sA + F_X + (uint32_t)(t & 1) * 4608;
#pragma unroll
        for (int ks = 0; ks < 4; ks++) {
            uint32_t ka = ks * 32;
            uint32_t bh[2][4];
#pragma unroll
            for (int j2 = 0; j2 < 2; j2++)
                ldsm_x4(bh[j2], sA + F_WIH + bOff + j2 * (16 * LP2) + ka);
#pragma unroll
            for (int i = 0; i < 2; i++) {
                uint32_t ah[4];
                ldsm_x4(ah, xb + aOff + i * (16 * LP2) + ka);
#pragma unroll
                for (int j = 0; j < 4; j++)
                    mma16816(acc[i][j], ah, &bh[j >> 1][(j & 1) * 2]);
            }
        }
        // pass 2: h @ Whh^T
#pragma unroll
        for (int ks = 0; ks < 4; ks++) {
            uint32_t ka = ks * 32;
            uint32_t bh[2][4];
#pragma unroll
            for (int j2 = 0; j2 < 2; j2++)
                ldsm_x4(bh[j2], sA + F_WHH + bOff + j2 * (16 * LP2) + ka);
#pragma unroll
            for (int i = 0; i < 2; i++) {
                uint32_t ah[4];
                ldsm_x4(ah, sA + F_H + aOff + i * (16 * LP2) + ka);
#pragma unroll
                for (int j = 0; j < 4; j++)
                    mma16816(acc[i][j], ah, &bh[j >> 1][(j & 1) * 2]);
            }
        }
        __syncthreads();   // all warps done reading h plane

        const float* bsm = (const float*)(sm + F_BIAS);
#pragma unroll
        for (int i = 0; i < 2; i++) {
#pragma unroll
            for (int rr = 0; rr < 2; rr++) {
                int row = i * 16 + rr * 8 + (lane >> 2);
                int n = nodeBase + row;
                bool valid = n < NN;
                int cb = wn * 32 + (lane & 3) * 2;
                float2 b0 = *(const float2*)(bsm + cb);
                float2 b1 = *(const float2*)(bsm + cb + 8);
                float2 b2 = *(const float2*)(bsm + cb + 16);
                float2 b3 = *(const float2*)(bsm + cb + 24);
                float hn2[2];
#pragma unroll
                for (int vv = 0; vv < 2; vv++) {
                    int w = i * 4 + rr * 2 + vv;
                    float gi = acc[i][0][rr * 2 + vv] + (vv ? b0.y : b0.x);
                    float gf = acc[i][1][rr * 2 + vv] + (vv ? b1.y : b1.x);
                    float gg = acc[i][2][rr * 2 + vv] + (vv ? b2.y : b2.x);
                    float go = acc[i][3][rr * 2 + vv] + (vv ? b3.y : b3.x);
                    float ig = sigmoidf_(gi);
                    float fg = sigmoidf_(gf);
                    float gt = tanhf_(gg);
                    float og = sigmoidf_(go);
                    float cn = fg * cst[w] + ig * gt;
                    cst[w] = cn;
                    hn2[vv] = og * tanhf_(cn);
                }
                int u = wn * 8 + (lane & 3) * 2;
                uint32_t hi2 = pack_h2(hn2[0], hn2[1]);
                *(uint32_t*)(sm + F_H + row * LP2 + u * 2) = hi2;
                if (valid) {
                    if (yH) {
                        size_t o = ((size_t)t * NN + n) * OUTD + u;
                        *(uint32_t*)(yH + o) = hi2;
                    }
                    if (outFinal && t == T_STEPS - 1)
                        *(float2*)(outFinal + (size_t)n * OUTD + u) =
                            make_float2(hn2[0], hn2[1]);
                }
            }
        }
        __syncthreads();
    }
}

// ===================== host =====================
extern "C" void kernel_launch(void* const* d_in, const int* in_sizes, int n_in,
                              void* d_out, int out_size) {
    const float* x   = (const float*)d_in[0];
    const int*   ei  = (const int*)d_in[1];
    const int*   src = ei;
    const int*   dst = ei + EE;
    const float* wg[3] = {(const float*)d_in[2], (const float*)d_in[4], (const float*)d_in[6]};
    const float* bg[3] = {(const float*)d_in[3], (const float*)d_in[5], (const float*)d_in[7]};
    const float* bnG[2] = {(const float*)d_in[8],  (const float*)d_in[12]};
    const float* bnB[2] = {(const float*)d_in[9],  (const float*)d_in[13]};
    const float* bnM[2] = {(const float*)d_in[10], (const float*)d_in[14]};
    const float* bnV[2] = {(const float*)d_in[11], (const float*)d_in[15]};
    const float* wih[3] = {(const float*)d_in[16], (const float*)d_in[20], (const float*)d_in[24]};
    const float* whh[3] = {(const float*)d_in[17], (const float*)d_in[21], (const float*)d_in[25]};
    const float* bih[3] = {(const float*)d_in[18], (const float*)d_in[22], (const float*)d_in[26]};
    const float* bhh[3] = {(const float*)d_in[19], (const float*)d_in[23], (const float*)d_in[27]};
    float* out = (float*)d_out;

    float* p_bias;
    __half *p_preH, *p_xH, *p_actA, *p_actB, *p_yA, *p_yB, *p_wH;
    cudaGetSymbolAddress((void**)&p_preH, g_preH);
    cudaGetSymbolAddress((void**)&p_xH,   g_xH);
    cudaGetSymbolAddress((void**)&p_bias, g_biasc);
    cudaGetSymbolAddress((void**)&p_actA, g_actA);
    cudaGetSymbolAddress((void**)&p_actB, g_actB);
    cudaGetSymbolAddress((void**)&p_yA,   g_yA);
    cudaGetSymbolAddress((void**)&p_yB,   g_yB);
    cudaGetSymbolAddress((void**)&p_wH,   g_wH);

    const int SM1 = 20480;   // K=32: single buffer (2 planes)
    const int SM2 = 40960;   // K=64/128: double buffer
    cudaFuncSetAttribute(k_gemm_mma<32>,  cudaFuncAttributeMaxDynamicSharedMemorySize, SM1);
    cudaFuncSetAttribute(k_gemm_mma<128>, cudaFuncAttributeMaxDynamicSharedMemorySize, SM2);
    cudaFuncSetAttribute(k_lstm_mma,   cudaFuncAttributeMaxDynamicSharedMemorySize, LSTM_MMA_SMEM);
    cudaFuncSetAttribute(k_lstm_fused, cudaFuncAttributeMaxDynamicSharedMemorySize, LSTM_FUSED_SMEM);

    // ---- setup ----
    k_zero_cnt<<<(NN + 255) / 256, 256>>>();
    k_hist<<<(EE + 255) / 256, 256>>>(dst);
    k_scanfused<<<1, 1024>>>();
    k_fillprep<<<FILL_BLOCKS + PREP_BLOCKS + XCONV_BLOCKS, 256>>>(
        src, dst, x, wg[0], wg[1], wg[2], wih[0], wih[1], wih[2],
        whh[0], whh[1], whh[2],
        bih[0], bhh[0], bih[1], bhh[1], bih[2], bhh[2]);

    const int MT = MROWS / 128;  // 625 M tiles

    // ---- GCN 0 ----
    k_agg32<<<NN, 256>>>(p_xH, p_actA);
    k_gemm_mma<32><<<dim3(MT, 1), 256, SM1>>>(
        p_actA, p_wH + WO0, bg[0],
        bnG[0], bnB[0], bnM[0], bnV[0], 2, HID, p_actB);
    // ---- GCN 1 ----
    k_aggh<<<NN, 256>>>(p_actB, p_actA);
    k_gemm_mma<128><<<dim3(MT, 1), 256, SM2>>>(
        p_actA, p_wH + WO1, bg[1],
        bnG[1], bnB[1], bnM[1], bnV[1], 2, HID, p_actB);
    // ---- GCN 2 (relu only) ----
    k_aggh<<<NN, 256>>>(p_actB, p_actA);
    k_gemm_mma<128><<<dim3(MT, 1), 256, SM2>>>(
        p_actA, p_wH + WO2, bg[2],
        nullptr, nullptr, nullptr, nullptr, 1, HID, p_actB);

    int lstmBlocks = (NN + 31) / 32;  // 313
    // ---- LSTM layer 0 (input GEMM + recurrence) ----
    k_gemm_mma<128><<<dim3(MT, 2), 256, SM2>>>(
        p_actB, p_wH + WO3, p_bias + 0 * G4,
        nullptr, nullptr, nullptr, nullptr, 0, G4, p_preH);
    k_lstm_mma<<<lstmBlocks, 256, LSTM_MMA_SMEM>>>(p_preH, p_wH + WH0, p_yA);
    // ---- LSTM layers 1 & 2 (fully fused) ----
    k_lstm_fused<<<lstmBlocks, 256, LSTM_FUSED_SMEM>>>(
        p_yA, p_wH + WO4, p_wH + WH1, p_bias + 1 * G4, p_yB, nullptr);
    k_lstm_fused<<<lstmBlocks, 256, LSTM_FUSED_SMEM>>>(
        p_yB, p_wH + WO5, p_wH + WH2, p_bias + 2 * G4, nullptr, out);
}